// round 3
// baseline (speedup 1.0000x reference)
#include <cuda_runtime.h>
#include <cuda_fp16.h>
#include <cstdint>

// Problem constants: P=8 segments, L=512 codes, D=64, N=1M tokens.
#define PP 8
#define LLEN 512
#define DD 64
#define CC (PP * LLEN)   // 4096 rows in transposed table

// Transposed + fp16-converted table: g_Wh[c][d] = (half)W[d][c].
// 4096 * 64 * 2B = 512 KB, L2-resident; rows are 128B contiguous.
__device__ __half g_Wh[CC * DD];

// ---------------------------------------------------------------------------
// Transpose+convert W [D=64, C=4096] fp32 -> g_Wh [C=4096, D=64] fp16.
// ---------------------------------------------------------------------------
__global__ void convert_w_kernel(const float* __restrict__ W) {
    int t = blockIdx.x * blockDim.x + threadIdx.x;   // 0 .. 262143
    int c = t & (CC - 1);
    int d = t >> 12;
    if (d < DD) {
        g_Wh[c * DD + d] = __float2half(W[d * CC + c]);
    }
}

// ---------------------------------------------------------------------------
// Gather-and-sum, fp16 table, fp32 accumulate.
// One warp = 4 tokens: tok = warp*4 + (lane>>3), s = lane&7.
// Row = 64 halfs = 128B = 8 lanes x LDG.128.
// __launch_bounds__(256, 8): force <=32 regs so 2048 threads/SM fit.
// ---------------------------------------------------------------------------
__global__ void __launch_bounds__(256, 8)
eif_gather_h_kernel(const int* __restrict__ x, float* __restrict__ out, int n_tok) {
    int warp_id = (blockIdx.x * blockDim.x + threadIdx.x) >> 5;
    int lane    = threadIdx.x & 31;
    int tok     = (warp_id << 2) + (lane >> 3);
    int s       = lane & 7;                      // 16B slot within the 128B row
    if (tok >= n_tok) return;

    // 8 int32 codes for this token (two 16B streaming loads, broadcast x8 lanes).
    const int4* xv = reinterpret_cast<const int4*>(x);
    int4 i0 = __ldcs(&xv[tok * 2 + 0]);
    int4 i1 = __ldcs(&xv[tok * 2 + 1]);

    // Base pointer for this lane's 16B slot; row stride = 8 uint4.
    const uint4* __restrict__ Wb = reinterpret_cast<const uint4*>(g_Wh) + s;

    // Issue all 8 gathers up front (independent -> MLP=8).
    uint4 v0 = Wb[(size_t)(0 * LLEN + i0.x) * 8];
    uint4 v1 = Wb[(size_t)(1 * LLEN + i0.y) * 8];
    uint4 v2 = Wb[(size_t)(2 * LLEN + i0.z) * 8];
    uint4 v3 = Wb[(size_t)(3 * LLEN + i0.w) * 8];
    uint4 v4 = Wb[(size_t)(4 * LLEN + i1.x) * 8];
    uint4 v5 = Wb[(size_t)(5 * LLEN + i1.y) * 8];
    uint4 v6 = Wb[(size_t)(6 * LLEN + i1.z) * 8];
    uint4 v7 = Wb[(size_t)(7 * LLEN + i1.w) * 8];

    // Pairwise fp16 add first (exact-enough: one extra rounding at half the
    // operand count) would save regs, but keep full fp32 accumulation:
    float2 a0 = make_float2(0.f, 0.f), a1 = make_float2(0.f, 0.f);
    float2 a2 = make_float2(0.f, 0.f), a3 = make_float2(0.f, 0.f);

#define ACC(v)                                                          \
    {                                                                   \
        float2 f0 = __half22float2(*reinterpret_cast<__half2*>(&v.x)); \
        float2 f1 = __half22float2(*reinterpret_cast<__half2*>(&v.y)); \
        float2 f2 = __half22float2(*reinterpret_cast<__half2*>(&v.z)); \
        float2 f3 = __half22float2(*reinterpret_cast<__half2*>(&v.w)); \
        a0.x += f0.x; a0.y += f0.y;                                     \
        a1.x += f1.x; a1.y += f1.y;                                     \
        a2.x += f2.x; a2.y += f2.y;                                     \
        a3.x += f3.x; a3.y += f3.y;                                     \
    }
    ACC(v0) ACC(v1) ACC(v2) ACC(v3) ACC(v4) ACC(v5) ACC(v6) ACC(v7)
#undef ACC

    // Streaming stores: output is write-once, keep it out of L2 as much as
    // possible so the gather table stays resident.
    float4* o = reinterpret_cast<float4*>(out + (size_t)tok * DD + s * 8);
    __stcs(&o[0], make_float4(a0.x, a0.y, a1.x, a1.y));
    __stcs(&o[1], make_float4(a2.x, a2.y, a3.x, a3.y));
}

// ---------------------------------------------------------------------------
// kernel_launch: d_in[0] = x (int32, N*8), d_in[1] = W (float32, 64*4096).
// ---------------------------------------------------------------------------
extern "C" void kernel_launch(void* const* d_in, const int* in_sizes, int n_in,
                              void* d_out, int out_size) {
    const int*   x = (const int*)d_in[0];
    const float* W = (const float*)d_in[1];
    float*       out = (float*)d_out;

    int n_tok = in_sizes[0] / PP;   // N

    // 1) Convert + transpose table to fp16.
    convert_w_kernel<<<(CC * DD) / 256, 256>>>(W);

    // 2) Gather-and-sum: 4 tokens/warp, 8 warps/block -> 32 tokens/block.
    {
        int threads = 256;
        long long warps_needed = ((long long)n_tok + 3) / 4;
        long long blocks = (warps_needed + 7) / 8;
        eif_gather_h_kernel<<<(unsigned)blocks, threads>>>(x, out, n_tok);
    }
}

// round 4
// speedup vs baseline: 1.0433x; 1.0433x over previous
#include <cuda_runtime.h>
#include <cuda_fp16.h>
#include <cstdint>

// Problem constants: P=8 segments, L=512 codes, D=64, N=1M tokens.
#define PP 8
#define LLEN 512
#define DD 64
#define CC (PP * LLEN)   // 4096 rows in transposed table

// Transposed + fp16-converted table: g_Wh[c][d] = (half)W[d][c].
// 4096 * 64 * 2B = 512 KB, L2-resident; rows are 128B contiguous.
__device__ __half g_Wh[CC * DD];

// ---------------------------------------------------------------------------
// Transpose+convert W [D=64, C=4096] fp32 -> g_Wh [C=4096, D=64] fp16.
// ---------------------------------------------------------------------------
__global__ void convert_w_kernel(const float* __restrict__ W) {
    int t = blockIdx.x * blockDim.x + threadIdx.x;   // 0 .. 262143
    int c = t & (CC - 1);
    int d = t >> 12;
    if (d < DD) {
        g_Wh[c * DD + d] = __float2half(W[d * CC + c]);
    }
}

// ---------------------------------------------------------------------------
// Gather-and-sum, fp16 table, two-level fp16 tree + fp32 final add.
// One warp = 4 tokens: tok = warp*4 + (lane>>3), s = lane&7.
// Row = 64 halfs = 128B = 8 lanes x LDG.128.
// No occupancy forcing (R3 showed higher occupancy hurts: L1tex queue contention).
// ---------------------------------------------------------------------------
__global__ void __launch_bounds__(256)
eif_gather_h_kernel(const int* __restrict__ x, float* __restrict__ out, int n_tok) {
    int warp_id = (blockIdx.x * blockDim.x + threadIdx.x) >> 5;
    int lane    = threadIdx.x & 31;
    int tok     = (warp_id << 2) + (lane >> 3);
    int s       = lane & 7;                      // 16B slot within the 128B row
    if (tok >= n_tok) return;

    // 8 int32 codes for this token (two 16B streaming loads, broadcast x8 lanes).
    const int4* xv = reinterpret_cast<const int4*>(x);
    int4 i0 = __ldcs(&xv[tok * 2 + 0]);
    int4 i1 = __ldcs(&xv[tok * 2 + 1]);

    // Base pointer for this lane's 16B slot; row stride = 8 uint4.
    const uint4* __restrict__ Wb = reinterpret_cast<const uint4*>(g_Wh) + s;

    // All 8 gathers in flight (MLP=8).
    uint4 v0 = Wb[(size_t)(0 * LLEN + i0.x) * 8];
    uint4 v1 = Wb[(size_t)(1 * LLEN + i0.y) * 8];
    uint4 v2 = Wb[(size_t)(2 * LLEN + i0.z) * 8];
    uint4 v3 = Wb[(size_t)(3 * LLEN + i0.w) * 8];
    uint4 v4 = Wb[(size_t)(4 * LLEN + i1.x) * 8];
    uint4 v5 = Wb[(size_t)(5 * LLEN + i1.y) * 8];
    uint4 v6 = Wb[(size_t)(6 * LLEN + i1.z) * 8];
    uint4 v7 = Wb[(size_t)(7 * LLEN + i1.w) * 8];

    // Treat each uint4 as 4x half2. Two fp16 tree levels, then fp32 finish.
    const __half2* h0 = reinterpret_cast<const __half2*>(&v0);
    const __half2* h1 = reinterpret_cast<const __half2*>(&v1);
    const __half2* h2 = reinterpret_cast<const __half2*>(&v2);
    const __half2* h3 = reinterpret_cast<const __half2*>(&v3);
    const __half2* h4 = reinterpret_cast<const __half2*>(&v4);
    const __half2* h5 = reinterpret_cast<const __half2*>(&v5);
    const __half2* h6 = reinterpret_cast<const __half2*>(&v6);
    const __half2* h7 = reinterpret_cast<const __half2*>(&v7);

    float4 o0, o1;
    float* of = reinterpret_cast<float*>(&o0);   // o0 then o1 contiguous? no —
    // write components explicitly instead:
    float res[8];
#pragma unroll
    for (int k = 0; k < 4; k++) {
        // Level 1 (fp16): 4 HADD2
        __half2 w01 = __hadd2(h0[k], h1[k]);
        __half2 w23 = __hadd2(h2[k], h3[k]);
        __half2 w45 = __hadd2(h4[k], h5[k]);
        __half2 w67 = __hadd2(h6[k], h7[k]);
        // Level 2 (fp16): 2 HADD2
        __half2 u0 = __hadd2(w01, w23);
        __half2 u1 = __hadd2(w45, w67);
        // Level 3 (fp32): convert + add
        float2 f0 = __half22float2(u0);
        float2 f1 = __half22float2(u1);
        res[2 * k + 0] = f0.x + f1.x;
        res[2 * k + 1] = f0.y + f1.y;
    }
    o0 = make_float4(res[0], res[1], res[2], res[3]);
    o1 = make_float4(res[4], res[5], res[6], res[7]);

    // Streaming stores: output is write-once; keep the table resident in L2.
    float4* o = reinterpret_cast<float4*>(out + (size_t)tok * DD + s * 8);
    __stcs(&o[0], o0);
    __stcs(&o[1], o1);
}

// ---------------------------------------------------------------------------
// kernel_launch: d_in[0] = x (int32, N*8), d_in[1] = W (float32, 64*4096).
// ---------------------------------------------------------------------------
extern "C" void kernel_launch(void* const* d_in, const int* in_sizes, int n_in,
                              void* d_out, int out_size) {
    const int*   x = (const int*)d_in[0];
    const float* W = (const float*)d_in[1];
    float*       out = (float*)d_out;

    int n_tok = in_sizes[0] / PP;   // N

    // 1) Convert + transpose table to fp16.
    convert_w_kernel<<<(CC * DD) / 256, 256>>>(W);

    // 2) Gather-and-sum: 4 tokens/warp, 8 warps/block -> 32 tokens/block.
    {
        int threads = 256;
        long long warps_needed = ((long long)n_tok + 3) / 4;
        long long blocks = (warps_needed + 7) / 8;
        eif_gather_h_kernel<<<(unsigned)blocks, threads>>>(x, out, n_tok);
    }
}

// round 5
// speedup vs baseline: 1.2928x; 1.2392x over previous
#include <cuda_runtime.h>
#include <cuda_fp16.h>
#include <cstdint>

// Problem constants: P=8 segments, L=512 codes, D=64, N=1M tokens.
#define PP 8
#define LLEN 512
#define DD 64
#define CC (PP * LLEN)   // 4096 rows in transposed table

// Transposed + fp16-converted table: g_Wh[c][d] = (half)W[d][c].
// 4096 * 64 * 2B = 512 KB, L2-resident; rows are 128B contiguous.
__device__ __half g_Wh[CC * DD];

// ---------------------------------------------------------------------------
// Transpose+convert W [D=64, C=4096] fp32 -> g_Wh [C=4096, D=64] fp16.
// One thread per table row c: reads are warp-coalesced (consecutive c at
// fixed d), writes are a fully-coalesced 128B row per thread.
// ---------------------------------------------------------------------------
__global__ void convert_w_kernel(const float* __restrict__ W) {
    int c = blockIdx.x * blockDim.x + threadIdx.x;   // 0 .. 4095
    if (c >= CC) return;

    __half hbuf[DD];
#pragma unroll
    for (int d = 0; d < DD; d++) {
        hbuf[d] = __float2half(W[d * CC + c]);
    }
    uint4* dst = reinterpret_cast<uint4*>(g_Wh + (size_t)c * DD);
    const uint4* src = reinterpret_cast<const uint4*>(hbuf);
#pragma unroll
    for (int k = 0; k < 8; k++) dst[k] = src[k];
}

// ---------------------------------------------------------------------------
// Gather-and-sum, fp16 table, two-level fp16 tree + fp32 finish.
// One warp = 2 tokens: t = lane>>4, s = lane&15 (8B slot in the 128B row).
// Each gather is one LDG.64 instruction covering row r for BOTH tokens:
// 32 lanes x 8B = 256B = 2 distinct lines -> minimal within-LDG replays
// at acceptable LSU issue count (4 LDG/token).
// ---------------------------------------------------------------------------
__global__ void __launch_bounds__(256)
eif_gather_h_kernel(const int* __restrict__ x, float* __restrict__ out, int n_tok) {
    int warp_id = (blockIdx.x * blockDim.x + threadIdx.x) >> 5;
    int lane    = threadIdx.x & 31;
    int t       = lane >> 4;                     // 0/1: which token of the pair
    int s       = lane & 15;                     // 8B slot within the 128B row
    int tok     = (warp_id << 1) + t;
    if (tok >= n_tok) return;

    // 8 int32 codes for this token (two 16B loads, broadcast over 16 lanes).
    const int4* xv = reinterpret_cast<const int4*>(x);
    int4 i0 = xv[tok * 2 + 0];
    int4 i1 = xv[tok * 2 + 1];

    // Lane's 8B slot; row stride = 16 uint2 (128B).
    const uint2* __restrict__ Wb = reinterpret_cast<const uint2*>(g_Wh) + s;

    // All 8 gathers in flight (MLP=8), each LDG.64, 2 lines per instruction.
    uint2 v0 = Wb[(size_t)(0 * LLEN + i0.x) * 16];
    uint2 v1 = Wb[(size_t)(1 * LLEN + i0.y) * 16];
    uint2 v2 = Wb[(size_t)(2 * LLEN + i0.z) * 16];
    uint2 v3 = Wb[(size_t)(3 * LLEN + i0.w) * 16];
    uint2 v4 = Wb[(size_t)(4 * LLEN + i1.x) * 16];
    uint2 v5 = Wb[(size_t)(5 * LLEN + i1.y) * 16];
    uint2 v6 = Wb[(size_t)(6 * LLEN + i1.z) * 16];
    uint2 v7 = Wb[(size_t)(7 * LLEN + i1.w) * 16];

    // Each uint2 = 2 half2 slots. Two fp16 tree levels, then fp32 finish.
    const __half2* h0 = reinterpret_cast<const __half2*>(&v0);
    const __half2* h1 = reinterpret_cast<const __half2*>(&v1);
    const __half2* h2 = reinterpret_cast<const __half2*>(&v2);
    const __half2* h3 = reinterpret_cast<const __half2*>(&v3);
    const __half2* h4 = reinterpret_cast<const __half2*>(&v4);
    const __half2* h5 = reinterpret_cast<const __half2*>(&v5);
    const __half2* h6 = reinterpret_cast<const __half2*>(&v6);
    const __half2* h7 = reinterpret_cast<const __half2*>(&v7);

    float res[4];
#pragma unroll
    for (int k = 0; k < 2; k++) {
        __half2 w01 = __hadd2(h0[k], h1[k]);
        __half2 w23 = __hadd2(h2[k], h3[k]);
        __half2 w45 = __hadd2(h4[k], h5[k]);
        __half2 w67 = __hadd2(h6[k], h7[k]);
        __half2 u0 = __hadd2(w01, w23);
        __half2 u1 = __hadd2(w45, w67);
        float2 f0 = __half22float2(u0);
        float2 f1 = __half22float2(u1);
        res[2 * k + 0] = f0.x + f1.x;
        res[2 * k + 1] = f0.y + f1.y;
    }

    // Lane s writes floats [4s, 4s+4) of this token's 64-float output row:
    // one STG.128 per warp covers both tokens' 256B rows.
    float4* o = reinterpret_cast<float4*>(out + (size_t)tok * DD + s * 4);
    __stcs(o, make_float4(res[0], res[1], res[2], res[3]));
}

// ---------------------------------------------------------------------------
// kernel_launch: d_in[0] = x (int32, N*8), d_in[1] = W (float32, 64*4096).
// ---------------------------------------------------------------------------
extern "C" void kernel_launch(void* const* d_in, const int* in_sizes, int n_in,
                              void* d_out, int out_size) {
    const int*   x = (const int*)d_in[0];
    const float* W = (const float*)d_in[1];
    float*       out = (float*)d_out;

    int n_tok = in_sizes[0] / PP;   // N

    // 1) Convert + transpose table to fp16 (coalesced reads AND writes).
    convert_w_kernel<<<CC / 256, 256>>>(W);

    // 2) Gather-and-sum: 2 tokens/warp, 8 warps/block -> 16 tokens/block.
    {
        int threads = 256;
        long long warps_needed = ((long long)n_tok + 1) / 2;
        long long blocks = (warps_needed + 7) / 8;
        eif_gather_h_kernel<<<(unsigned)blocks, threads>>>(x, out, n_tok);
    }
}